// round 3
// baseline (speedup 1.0000x reference)
#include <cuda_runtime.h>
#include <cuda_bf16.h>
#include <math.h>

// Problem constants
#define BB 128
#define HH 512
#define WW 512
#define PP 64
#define DD 4
#define NHW (HH * WW)          // 262144 elems per batch image
#define EPSV 1e-5f

// ---------------------------------------------------------------------------
// Scratch (device globals — no dynamic allocation allowed)
// ---------------------------------------------------------------------------
static __device__ float g_Wj[512 * 512];                 // concat(o_rel_xj | p_xi)  [k=w][n]
static __device__ float g_Wi[512 * 512];                 // concat(o_rel_xi | p_xj)  [k=h][n]
static __device__ float g_U[(size_t)BB * 512 * 512];     // x_b @ Wj      [b][h][n]
static __device__ float g_V[(size_t)BB * 512 * 512];     // x_b^T @ Wi    [b][w][n]
static __device__ float g_pt[(size_t)BB * 2 * DD * PP * PP];  // p_t_{xj,xi} [b][branch][d][p1][p2]
static __device__ float g_orel[(size_t)BB * 2 * DD * PP];     // o_rel sums  [b][branch][d][p]
static __device__ float g_prel[(size_t)BB * 2 * DD * PP];     // p_rel sums  [b][branch][d][p]
static __device__ float g_stats[BB * 2];                      // [b]{mean*64, std*64}

// ---------------------------------------------------------------------------
// K0: build concatenated weight matrices
//   Wj[k][n]: n<256 -> o_rel_xj[d][k][p], n>=256 -> p_xi[d][k][p]
//   Wi[k][n]: n<256 -> o_rel_xi[d][k][p], n>=256 -> p_xj[d][k][p]
//   (d = (n>>6)&3, p = n&63)
// ---------------------------------------------------------------------------
__global__ void prep_kernel(const float* __restrict__ o_rel_xj,
                            const float* __restrict__ p_xi,
                            const float* __restrict__ o_rel_xi,
                            const float* __restrict__ p_xj) {
    int idx = blockIdx.x * 256 + threadIdx.x;   // < 512*512
    int k = idx >> 9;
    int n = idx & 511;
    int d = (n >> 6) & 3;
    int p = n & 63;
    int widx = (d * 512 + k) * 64 + p;
    if (n < 256) {
        g_Wj[idx] = o_rel_xj[widx];
        g_Wi[idx] = o_rel_xi[widx];
    } else {
        g_Wj[idx] = p_xi[widx];
        g_Wi[idx] = p_xj[widx];
    }
}

// ---------------------------------------------------------------------------
// K_stats: per-batch mean*scale and unbiased std*scale of x (scale = 64)
// ---------------------------------------------------------------------------
__global__ __launch_bounds__(256) void stats_kernel(const float* __restrict__ x) {
    int b = blockIdx.x;
    const float4* xb4 = (const float4*)(x + (size_t)b * NHW);
    int tid = threadIdx.x;
    float s = 0.f, s2 = 0.f;
    for (int i = tid; i < NHW / 4; i += 256) {
        float4 v = xb4[i];
        s  += v.x + v.y + v.z + v.w;
        s2 += v.x * v.x + v.y * v.y + v.z * v.z + v.w * v.w;
    }
    __shared__ float rs[256], rs2[256];
    rs[tid] = s; rs2[tid] = s2;
    __syncthreads();
    for (int st = 128; st > 0; st >>= 1) {
        if (tid < st) { rs[tid] += rs[tid + st]; rs2[tid] += rs2[tid + st]; }
        __syncthreads();
    }
    if (tid == 0) {
        float n = (float)NHW;
        float sum = rs[0], sumsq = rs2[0];
        float mean = sum / n;
        float var = (sumsq - sum * sum / n) / (n - 1.0f);
        g_stats[b * 2 + 0] = mean * 64.0f;
        g_stats[b * 2 + 1] = sqrtf(var) * 64.0f;
    }
}

// ---------------------------------------------------------------------------
// K1/K2: per-batch 512x512x512 fp32 GEMM, CTA tile 128x128, thread tile 8x8.
//   TRANSA=false: C = x_b   @ g_Wj  -> g_U   (A[m,k] = x_b[m*512+k])
//   TRANSA=true : C = x_b^T @ g_Wi  -> g_V   (A[m,k] = x_b[k*512+m], coalesced)
// ---------------------------------------------------------------------------
template <bool TRANSA>
__global__ __launch_bounds__(256) void gemm_s1(const float* __restrict__ X) {
    const int b  = blockIdx.z;
    const float* A = X + (size_t)b * NHW;
    const float* Wc = TRANSA ? g_Wi : g_Wj;
    float* C = (TRANSA ? g_V : g_U) + (size_t)b * NHW;

    const int bm = blockIdx.y * 128;
    const int bn = blockIdx.x * 128;

    __shared__ float As[16][132];
    __shared__ float Bs[16][132];

    const int tid = threadIdx.x;
    const int r = tid >> 4;       // 0..15
    const int c = tid & 15;       // 0..15

    float acc[8][8];
#pragma unroll
    for (int i = 0; i < 8; i++)
#pragma unroll
        for (int j = 0; j < 8; j++) acc[i][j] = 0.f;

    for (int k0 = 0; k0 < 512; k0 += 16) {
        // ---- load A tile (128 m x 16 k) into As[k][m] ----
        if (!TRANSA) {
            int m  = tid >> 1;              // 0..127
            int kq = (tid & 1) * 8;         // 0 or 8
            const float* ap = &A[(size_t)(bm + m) * 512 + k0 + kq];
            float4 v0 = *(const float4*)(ap);
            float4 v1 = *(const float4*)(ap + 4);
            As[kq + 0][m] = v0.x; As[kq + 1][m] = v0.y;
            As[kq + 2][m] = v0.z; As[kq + 3][m] = v0.w;
            As[kq + 4][m] = v1.x; As[kq + 5][m] = v1.y;
            As[kq + 6][m] = v1.z; As[kq + 7][m] = v1.w;
        } else {
            int k  = tid >> 4;              // 0..15
            int mq = (tid & 15) * 8;        // 0..120
            const float* ap = &A[(size_t)(k0 + k) * 512 + bm + mq];
            float4 v0 = *(const float4*)(ap);
            float4 v1 = *(const float4*)(ap + 4);
            *(float4*)&As[k][mq]     = v0;
            *(float4*)&As[k][mq + 4] = v1;
        }
        // ---- load B tile (16 k x 128 n) into Bs[k][n] ----
        {
            int k  = tid >> 4;
            int nq = (tid & 15) * 8;
            const float* bp = &Wc[(size_t)(k0 + k) * 512 + bn + nq];
            float4 v0 = *(const float4*)(bp);
            float4 v1 = *(const float4*)(bp + 4);
            *(float4*)&Bs[k][nq]     = v0;
            *(float4*)&Bs[k][nq + 4] = v1;
        }
        __syncthreads();

#pragma unroll
        for (int k = 0; k < 16; k++) {
            float a[8], bv[8];
            *(float4*)&a[0]  = *(float4*)&As[k][r * 4];
            *(float4*)&a[4]  = *(float4*)&As[k][64 + r * 4];
            *(float4*)&bv[0] = *(float4*)&Bs[k][c * 4];
            *(float4*)&bv[4] = *(float4*)&Bs[k][64 + c * 4];
#pragma unroll
            for (int i = 0; i < 8; i++)
#pragma unroll
                for (int j = 0; j < 8; j++) acc[i][j] += a[i] * bv[j];
        }
        __syncthreads();
    }

    // ---- store ----
#pragma unroll
    for (int i = 0; i < 8; i++) {
        int m = bm + ((i < 4) ? (r * 4 + i) : (64 + r * 4 + (i - 4)));
        float4 v0 = make_float4(acc[i][0], acc[i][1], acc[i][2], acc[i][3]);
        float4 v1 = make_float4(acc[i][4], acc[i][5], acc[i][6], acc[i][7]);
        *(float4*)&C[(size_t)m * 512 + bn + c * 4]      = v0;
        *(float4*)&C[(size_t)m * 512 + bn + 64 + c * 4] = v1;
    }
}

// ---------------------------------------------------------------------------
// K3: o_rel flat-softmax column sums over [512,64] slabs of U (branch j) /
//     V (branch i). g_orel[b][branch][d][p] = sum_rows exp / sum_all exp.
// ---------------------------------------------------------------------------
__global__ __launch_bounds__(256) void rel1_kernel() {
    int blk = blockIdx.x;
    int b = blk >> 3;
    int branch = (blk >> 2) & 1;   // 0: j (U), 1: i (V)
    int d = blk & 3;
    const float* base = (branch ? g_V : g_U) + (size_t)b * NHW + d * 64;

    int tid = threadIdx.x;
    int p  = tid & 63;
    int rg = tid >> 6;   // 0..3

    __shared__ float red[256];
    __shared__ float cs[64];

    float mx = -1e30f;
    for (int h = rg; h < 512; h += 4)
        mx = fmaxf(mx, base[(size_t)h * 512 + p]);
    red[tid] = mx;
    __syncthreads();
    for (int s = 128; s > 0; s >>= 1) {
        if (tid < s) red[tid] = fmaxf(red[tid], red[tid + s]);
        __syncthreads();
    }
    float gmax = red[0];
    __syncthreads();

    float se = 0.f;
    for (int h = rg; h < 512; h += 4)
        se += expf(base[(size_t)h * 512 + p] - gmax);
    red[tid] = se;
    __syncthreads();
    if (tid < 64)
        cs[tid] = red[tid] + red[64 + tid] + red[128 + tid] + red[192 + tid];
    __syncthreads();
    if (tid == 0) {
        float t = 0.f;
        for (int i = 0; i < 64; i++) t += cs[i];
        red[0] = t;
    }
    __syncthreads();
    if (tid < 64)
        g_orel[(((size_t)b * 2 + branch) * DD + d) * 64 + tid] = cs[tid] / red[0];
}

// ---------------------------------------------------------------------------
// K4: small GEMMs.  p_t[b][branch][d] (64x64):
//   branch j: sum_w o_xj[d][w][p1] * V[b][w][256 + 64d + p2]
//   branch i: sum_h o_xi[d][h][p1] * U[b][h][256 + 64d + p2]
// ---------------------------------------------------------------------------
__global__ __launch_bounds__(256) void pt_gemm_kernel(const float* __restrict__ o_xj,
                                                      const float* __restrict__ o_xi) {
    int blk = blockIdx.x;
    int b = blk >> 3;
    int branch = (blk >> 2) & 1;
    int d = blk & 3;
    const float* Aw = (branch == 0 ? o_xj : o_xi) + (size_t)d * 512 * 64;
    const float* Bm = (branch == 0 ? g_V : g_U) + (size_t)b * NHW + 256 + d * 64;

    __shared__ float As[32][68];
    __shared__ float Bs[32][68];

    int tid = threadIdx.x;
    int r = tid >> 4, c = tid & 15;
    float acc[4][4];
#pragma unroll
    for (int i = 0; i < 4; i++)
#pragma unroll
        for (int j = 0; j < 4; j++) acc[i][j] = 0.f;

    for (int k0 = 0; k0 < 512; k0 += 32) {
        int k  = tid >> 3;          // 0..31
        int pq = (tid & 7) * 8;     // 0..56
        float4 a0 = *(const float4*)&Aw[(size_t)(k0 + k) * 64 + pq];
        float4 a1 = *(const float4*)&Aw[(size_t)(k0 + k) * 64 + pq + 4];
        *(float4*)&As[k][pq]     = a0;
        *(float4*)&As[k][pq + 4] = a1;
        float4 b0 = *(const float4*)&Bm[(size_t)(k0 + k) * 512 + pq];
        float4 b1 = *(const float4*)&Bm[(size_t)(k0 + k) * 512 + pq + 4];
        *(float4*)&Bs[k][pq]     = b0;
        *(float4*)&Bs[k][pq + 4] = b1;
        __syncthreads();
#pragma unroll
        for (int k2 = 0; k2 < 32; k2++) {
            float a[4], bv[4];
            *(float4*)&a[0]  = *(float4*)&As[k2][r * 4];
            *(float4*)&bv[0] = *(float4*)&Bs[k2][c * 4];
#pragma unroll
            for (int i = 0; i < 4; i++)
#pragma unroll
                for (int j = 0; j < 4; j++) acc[i][j] += a[i] * bv[j];
        }
        __syncthreads();
    }

    float* out = g_pt + (((size_t)b * 2 + branch) * DD + d) * 4096;
#pragma unroll
    for (int i = 0; i < 4; i++) {
        float4 v = make_float4(acc[i][0], acc[i][1], acc[i][2], acc[i][3]);
        *(float4*)&out[(size_t)(r * 4 + i) * 64 + c * 4] = v;
    }
}

// ---------------------------------------------------------------------------
// K5: G = p_t @ p_rel  (64x64 @ 64x64), then flat-softmax column sums.
// ---------------------------------------------------------------------------
__global__ __launch_bounds__(256) void prel_kernel(const float* __restrict__ p_rel_xj,
                                                   const float* __restrict__ p_rel_xi) {
    int blk = blockIdx.x;
    int b = blk >> 3;
    int branch = (blk >> 2) & 1;
    int d = blk & 3;
    const float* A = g_pt + (((size_t)b * 2 + branch) * DD + d) * 4096;  // [64,64]
    const float* R = (branch == 0 ? p_rel_xj : p_rel_xi) + (size_t)d * 4096;

    __shared__ float As[4096];
    __shared__ float Rs[4096];
    __shared__ float red[256];
    __shared__ float cs[64];

    int tid = threadIdx.x;
    for (int i = tid; i < 4096; i += 256) { As[i] = A[i]; Rs[i] = R[i]; }
    __syncthreads();

    int r = tid >> 4, c = tid & 15;
    float g[4][4];
#pragma unroll
    for (int i = 0; i < 4; i++)
#pragma unroll
        for (int j = 0; j < 4; j++) g[i][j] = 0.f;
    for (int k = 0; k < 64; k++) {
        float a[4], bv[4];
#pragma unroll
        for (int i = 0; i < 4; i++) a[i] = As[(r * 4 + i) * 64 + k];
#pragma unroll
        for (int j = 0; j < 4; j++) bv[j] = Rs[k * 64 + c * 4 + j];
#pragma unroll
        for (int i = 0; i < 4; i++)
#pragma unroll
            for (int j = 0; j < 4; j++) g[i][j] += a[i] * bv[j];
    }
    __syncthreads();            // done reading As; repurpose as G storage
#pragma unroll
    for (int i = 0; i < 4; i++)
#pragma unroll
        for (int j = 0; j < 4; j++)
            As[(r * 4 + i) * 64 + c * 4 + j] = g[i][j];
    __syncthreads();

    // flat softmax column sums over As[64][64]
    int p  = tid & 63;
    int rg = tid >> 6;  // 0..3
    float mx = -1e30f;
    for (int row = rg; row < 64; row += 4)
        mx = fmaxf(mx, As[row * 64 + p]);
    red[tid] = mx;
    __syncthreads();
    for (int s = 128; s > 0; s >>= 1) {
        if (tid < s) red[tid] = fmaxf(red[tid], red[tid + s]);
        __syncthreads();
    }
    float gmax = red[0];
    __syncthreads();
    float se = 0.f;
    for (int row = rg; row < 64; row += 4)
        se += expf(As[row * 64 + p] - gmax);
    red[tid] = se;
    __syncthreads();
    if (tid < 64)
        cs[tid] = red[tid] + red[64 + tid] + red[128 + tid] + red[192 + tid];
    __syncthreads();
    if (tid == 0) {
        float t = 0.f;
        for (int i = 0; i < 64; i++) t += cs[i];
        red[0] = t;
    }
    __syncthreads();
    if (tid < 64)
        g_prel[(((size_t)b * 2 + branch) * DD + d) * 64 + tid] = cs[tid] / red[0];
}

// ---------------------------------------------------------------------------
// K6: final combine per batch:
//  for d: x_buf = p_t_xj * f_j[p1] + (p_t_xi * f_i)[p2,p1];
//         renorm to (mean 0, std 1 ddof=1) then scale by x_std + x_mean; acc.
// ---------------------------------------------------------------------------
__global__ __launch_bounds__(256) void final_kernel(float* __restrict__ out) {
    int b = blockIdx.x;
    int tid = threadIdx.x;
    __shared__ float fj[64], fi[64];
    __shared__ float red[256], red2[256];

    float accv[16];
#pragma unroll
    for (int i = 0; i < 16; i++) accv[i] = 0.f;

    float xm = g_stats[b * 2 + 0];
    float xs = g_stats[b * 2 + 1];

    for (int d = 0; d < DD; d++) {
        __syncthreads();
        if (tid < 64) {
            size_t ij = (((size_t)b * 2 + 0) * DD + d) * 64 + tid;
            fj[tid] = sqrtf(g_orel[ij] / g_prel[ij]);
        } else if (tid < 128) {
            int p = tid - 64;
            size_t ii = (((size_t)b * 2 + 1) * DD + d) * 64 + p;
            fi[p] = sqrtf(g_orel[ii] / g_prel[ii]);
        }
        __syncthreads();

        const float* ptj = g_pt + (((size_t)b * 2 + 0) * DD + d) * 4096;
        const float* pti = g_pt + (((size_t)b * 2 + 1) * DD + d) * 4096;

        float v[16];
        float s = 0.f, s2 = 0.f;
#pragma unroll
        for (int i = 0; i < 16; i++) {
            int e = i * 256 + tid;
            int p1 = e >> 6, p2 = e & 63;
            float val = ptj[e] * fj[p1] + pti[p2 * 64 + p1] * fi[p2];
            v[i] = val;
            s += val;
            s2 += val * val;
        }
        red[tid] = s; red2[tid] = s2;
        __syncthreads();
        for (int st = 128; st > 0; st >>= 1) {
            if (tid < st) { red[tid] += red[tid + st]; red2[tid] += red2[tid + st]; }
            __syncthreads();
        }
        float sum = red[0], sumsq = red2[0];
        float mu = sum / 4096.0f;
        float var = (sumsq - sum * sum / 4096.0f) / 4095.0f;
        float inv = 1.0f / (sqrtf(var) + EPSV);
#pragma unroll
        for (int i = 0; i < 16; i++)
            accv[i] += (v[i] - mu) * inv * xs + xm;
        __syncthreads();
    }

#pragma unroll
    for (int i = 0; i < 16; i++)
        out[(size_t)b * 4096 + i * 256 + tid] = accv[i];
}

// ---------------------------------------------------------------------------
// Launch
// ---------------------------------------------------------------------------
extern "C" void kernel_launch(void* const* d_in, const int* in_sizes, int n_in,
                              void* d_out, int out_size) {
    const float* x        = (const float*)d_in[0];
    const float* o_xj     = (const float*)d_in[1];
    const float* o_xi     = (const float*)d_in[2];
    const float* p_xj     = (const float*)d_in[3];
    const float* p_xi     = (const float*)d_in[4];
    const float* o_rel_xj = (const float*)d_in[5];
    const float* o_rel_xi = (const float*)d_in[6];
    const float* p_rel_xj = (const float*)d_in[7];
    const float* p_rel_xi = (const float*)d_in[8];
    float* out = (float*)d_out;

    prep_kernel<<<(512 * 512) / 256, 256>>>(o_rel_xj, p_xi, o_rel_xi, p_xj);
    stats_kernel<<<BB, 256>>>(x);
    gemm_s1<false><<<dim3(4, 4, BB), 256>>>(x);   // U = x_b @ Wj
    gemm_s1<true><<<dim3(4, 4, BB), 256>>>(x);    // V = x_b^T @ Wi
    rel1_kernel<<<BB * 8, 256>>>();
    pt_gemm_kernel<<<BB * 8, 256>>>(o_xj, o_xi);
    prel_kernel<<<BB * 8, 256>>>(p_rel_xj, p_rel_xi);
    final_kernel<<<BB, 256>>>(out);
}

// round 16
// speedup vs baseline: 1.0892x; 1.0892x over previous
#include <cuda_runtime.h>
#include <cuda_bf16.h>
#include <math.h>
#include <stdint.h>

// Problem constants
#define BB 128
#define HH 512
#define WW 512
#define PP 64
#define DD 4
#define NHW (HH * WW)          // 262144 elems per batch image
#define EPSV 1e-5f

// ---------------------------------------------------------------------------
// Scratch (device globals — no dynamic allocation allowed)
// ---------------------------------------------------------------------------
static __device__ float g_Wj[512 * 512];                 // concat(o_rel_xj | p_xi)  [k=w][n]
static __device__ float g_Wi[512 * 512];                 // concat(o_rel_xi | p_xj)  [k=h][n]
static __device__ float g_U[(size_t)BB * 512 * 512];     // x_b @ Wj      [b][h][n]
static __device__ float g_V[(size_t)BB * 512 * 512];     // x_b^T @ Wi    [b][w][n]
static __device__ float g_pt[(size_t)BB * 2 * DD * PP * PP];  // p_t_{xj,xi}
static __device__ float g_orel[(size_t)BB * 2 * DD * PP];
static __device__ float g_prel[(size_t)BB * 2 * DD * PP];
static __device__ float g_stats[BB * 2];

union F4U {
    float4 f;
    unsigned long long u[2];
};

// ---------------------------------------------------------------------------
// K0: build concatenated weight matrices
// ---------------------------------------------------------------------------
__global__ void prep_kernel(const float* __restrict__ o_rel_xj,
                            const float* __restrict__ p_xi,
                            const float* __restrict__ o_rel_xi,
                            const float* __restrict__ p_xj) {
    int idx = blockIdx.x * 256 + threadIdx.x;   // < 512*512
    int k = idx >> 9;
    int n = idx & 511;
    int d = (n >> 6) & 3;
    int p = n & 63;
    int widx = (d * 512 + k) * 64 + p;
    if (n < 256) {
        g_Wj[idx] = o_rel_xj[widx];
        g_Wi[idx] = o_rel_xi[widx];
    } else {
        g_Wj[idx] = p_xi[widx];
        g_Wi[idx] = p_xj[widx];
    }
}

// ---------------------------------------------------------------------------
// stats: per-batch mean*64 and unbiased std*64 of x
// ---------------------------------------------------------------------------
__global__ __launch_bounds__(256) void stats_kernel(const float* __restrict__ x) {
    int b = blockIdx.x;
    const float4* xb4 = (const float4*)(x + (size_t)b * NHW);
    int tid = threadIdx.x;
    float s = 0.f, s2 = 0.f;
    for (int i = tid; i < NHW / 4; i += 256) {
        float4 v = xb4[i];
        s  += v.x + v.y + v.z + v.w;
        s2 += v.x * v.x + v.y * v.y + v.z * v.z + v.w * v.w;
    }
    __shared__ float rs[256], rs2[256];
    rs[tid] = s; rs2[tid] = s2;
    __syncthreads();
    for (int st = 128; st > 0; st >>= 1) {
        if (tid < st) { rs[tid] += rs[tid + st]; rs2[tid] += rs2[tid + st]; }
        __syncthreads();
    }
    if (tid == 0) {
        float n = (float)NHW;
        float sum = rs[0], sumsq = rs2[0];
        float mean = sum / n;
        float var = (sumsq - sum * sum / n) / (n - 1.0f);
        g_stats[b * 2 + 0] = mean * 64.0f;
        g_stats[b * 2 + 1] = sqrtf(var) * 64.0f;
    }
}

// ---------------------------------------------------------------------------
// K1/K2: per-batch 512x512x512 fp32 GEMM, CTA tile 128x128, thread tile 8x8.
// Inner product uses packed fma.rn.f32x2 (Blackwell FFMA2): 32 packed FMAs
// per k-step instead of 64 scalar FFMA. Numerics identical to fp32.
// ---------------------------------------------------------------------------
template <bool TRANSA>
__global__ __launch_bounds__(256) void gemm_s1(const float* __restrict__ X) {
    const int b  = blockIdx.z;
    const float* A = X + (size_t)b * NHW;
    const float* Wc = TRANSA ? g_Wi : g_Wj;
    float* C = (TRANSA ? g_V : g_U) + (size_t)b * NHW;

    const int bm = blockIdx.y * 128;
    const int bn = blockIdx.x * 128;

    __shared__ float As[16][132];
    __shared__ float Bs[16][132];

    const int tid = threadIdx.x;
    const int r = tid >> 4;       // 0..15
    const int c = tid & 15;       // 0..15

    // acc2[i][j] packs columns {2j, 2j+1} of the 8-wide row i (as two fp32)
    unsigned long long acc2[8][4];
#pragma unroll
    for (int i = 0; i < 8; i++)
#pragma unroll
        for (int j = 0; j < 4; j++) acc2[i][j] = 0ull;  // (+0.0f, +0.0f)

    for (int k0 = 0; k0 < 512; k0 += 16) {
        // ---- load A tile (128 m x 16 k) into As[k][m] ----
        if (!TRANSA) {
            int m  = tid >> 1;              // 0..127
            int kq = (tid & 1) * 8;         // 0 or 8
            const float* ap = &A[(size_t)(bm + m) * 512 + k0 + kq];
            float4 v0 = *(const float4*)(ap);
            float4 v1 = *(const float4*)(ap + 4);
            As[kq + 0][m] = v0.x; As[kq + 1][m] = v0.y;
            As[kq + 2][m] = v0.z; As[kq + 3][m] = v0.w;
            As[kq + 4][m] = v1.x; As[kq + 5][m] = v1.y;
            As[kq + 6][m] = v1.z; As[kq + 7][m] = v1.w;
        } else {
            int k  = tid >> 4;              // 0..15
            int mq = (tid & 15) * 8;        // 0..120
            const float* ap = &A[(size_t)(k0 + k) * 512 + bm + mq];
            float4 v0 = *(const float4*)(ap);
            float4 v1 = *(const float4*)(ap + 4);
            *(float4*)&As[k][mq]     = v0;
            *(float4*)&As[k][mq + 4] = v1;
        }
        // ---- load B tile (16 k x 128 n) into Bs[k][n] ----
        {
            int k  = tid >> 4;
            int nq = (tid & 15) * 8;
            const float* bp = &Wc[(size_t)(k0 + k) * 512 + bn + nq];
            float4 v0 = *(const float4*)(bp);
            float4 v1 = *(const float4*)(bp + 4);
            *(float4*)&Bs[k][nq]     = v0;
            *(float4*)&Bs[k][nq + 4] = v1;
        }
        __syncthreads();

#pragma unroll
        for (int k = 0; k < 16; k++) {
            float a[8];
            *(float4*)&a[0] = *(float4*)&As[k][r * 4];
            *(float4*)&a[4] = *(float4*)&As[k][64 + r * 4];
            F4U bu0, bu1;
            bu0.f = *(float4*)&Bs[k][c * 4];
            bu1.f = *(float4*)&Bs[k][64 + c * 4];
            unsigned long long bp0 = bu0.u[0], bp1 = bu0.u[1];
            unsigned long long bp2 = bu1.u[0], bp3 = bu1.u[1];
#pragma unroll
            for (int i = 0; i < 8; i++) {
                unsigned long long ad;
                asm("mov.b64 %0, {%1, %1};" : "=l"(ad) : "f"(a[i]));
                asm("fma.rn.f32x2 %0, %1, %2, %0;" : "+l"(acc2[i][0]) : "l"(ad), "l"(bp0));
                asm("fma.rn.f32x2 %0, %1, %2, %0;" : "+l"(acc2[i][1]) : "l"(ad), "l"(bp1));
                asm("fma.rn.f32x2 %0, %1, %2, %0;" : "+l"(acc2[i][2]) : "l"(ad), "l"(bp2));
                asm("fma.rn.f32x2 %0, %1, %2, %0;" : "+l"(acc2[i][3]) : "l"(ad), "l"(bp3));
            }
        }
        __syncthreads();
    }

    // ---- store ----
#pragma unroll
    for (int i = 0; i < 8; i++) {
        int m = bm + ((i < 4) ? (r * 4 + i) : (64 + r * 4 + (i - 4)));
        F4U v0, v1;
        v0.u[0] = acc2[i][0]; v0.u[1] = acc2[i][1];
        v1.u[0] = acc2[i][2]; v1.u[1] = acc2[i][3];
        *(float4*)&C[(size_t)m * 512 + bn + c * 4]      = v0.f;
        *(float4*)&C[(size_t)m * 512 + bn + 64 + c * 4] = v1.f;
    }
}

// ---------------------------------------------------------------------------
// K3: o_rel flat-softmax column sums over [512,64] slabs of U / V.
// ---------------------------------------------------------------------------
__global__ __launch_bounds__(256) void rel1_kernel() {
    int blk = blockIdx.x;
    int b = blk >> 3;
    int branch = (blk >> 2) & 1;   // 0: j (U), 1: i (V)
    int d = blk & 3;
    const float* base = (branch ? g_V : g_U) + (size_t)b * NHW + d * 64;

    int tid = threadIdx.x;
    int p  = tid & 63;
    int rg = tid >> 6;   // 0..3

    __shared__ float red[256];
    __shared__ float cs[64];

    float mx = -1e30f;
    for (int h = rg; h < 512; h += 4)
        mx = fmaxf(mx, base[(size_t)h * 512 + p]);
    red[tid] = mx;
    __syncthreads();
    for (int s = 128; s > 0; s >>= 1) {
        if (tid < s) red[tid] = fmaxf(red[tid], red[tid + s]);
        __syncthreads();
    }
    float gmax = red[0];
    __syncthreads();

    float se = 0.f;
    for (int h = rg; h < 512; h += 4)
        se += expf(base[(size_t)h * 512 + p] - gmax);
    red[tid] = se;
    __syncthreads();
    if (tid < 64)
        cs[tid] = red[tid] + red[64 + tid] + red[128 + tid] + red[192 + tid];
    __syncthreads();
    if (tid == 0) {
        float t = 0.f;
        for (int i = 0; i < 64; i++) t += cs[i];
        red[0] = t;
    }
    __syncthreads();
    if (tid < 64)
        g_orel[(((size_t)b * 2 + branch) * DD + d) * 64 + tid] = cs[tid] / red[0];
}

// ---------------------------------------------------------------------------
// K4: small GEMMs. p_t[b][branch][d] (64x64)
// ---------------------------------------------------------------------------
__global__ __launch_bounds__(256) void pt_gemm_kernel(const float* __restrict__ o_xj,
                                                      const float* __restrict__ o_xi) {
    int blk = blockIdx.x;
    int b = blk >> 3;
    int branch = (blk >> 2) & 1;
    int d = blk & 3;
    const float* Aw = (branch == 0 ? o_xj : o_xi) + (size_t)d * 512 * 64;
    const float* Bm = (branch == 0 ? g_V : g_U) + (size_t)b * NHW + 256 + d * 64;

    __shared__ float As[32][68];
    __shared__ float Bs[32][68];

    int tid = threadIdx.x;
    int r = tid >> 4, c = tid & 15;
    float acc[4][4];
#pragma unroll
    for (int i = 0; i < 4; i++)
#pragma unroll
        for (int j = 0; j < 4; j++) acc[i][j] = 0.f;

    for (int k0 = 0; k0 < 512; k0 += 32) {
        int k  = tid >> 3;          // 0..31
        int pq = (tid & 7) * 8;     // 0..56
        float4 a0 = *(const float4*)&Aw[(size_t)(k0 + k) * 64 + pq];
        float4 a1 = *(const float4*)&Aw[(size_t)(k0 + k) * 64 + pq + 4];
        *(float4*)&As[k][pq]     = a0;
        *(float4*)&As[k][pq + 4] = a1;
        float4 b0 = *(const float4*)&Bm[(size_t)(k0 + k) * 512 + pq];
        float4 b1 = *(const float4*)&Bm[(size_t)(k0 + k) * 512 + pq + 4];
        *(float4*)&Bs[k][pq]     = b0;
        *(float4*)&Bs[k][pq + 4] = b1;
        __syncthreads();
#pragma unroll
        for (int k2 = 0; k2 < 32; k2++) {
            float a[4], bv[4];
#pragma unroll
            for (int i = 0; i < 4; i++) a[i] = As[k2][r * 4 + i];
#pragma unroll
            for (int j = 0; j < 4; j++) bv[j] = Bs[k2][c * 4 + j];
#pragma unroll
            for (int i = 0; i < 4; i++)
#pragma unroll
                for (int j = 0; j < 4; j++) acc[i][j] += a[i] * bv[j];
        }
        __syncthreads();
    }

    float* out = g_pt + (((size_t)b * 2 + branch) * DD + d) * 4096;
#pragma unroll
    for (int i = 0; i < 4; i++) {
        float4 v = make_float4(acc[i][0], acc[i][1], acc[i][2], acc[i][3]);
        *(float4*)&out[(size_t)(r * 4 + i) * 64 + c * 4] = v;
    }
}

// ---------------------------------------------------------------------------
// K5: G = p_t @ p_rel (64x64), then flat-softmax column sums.
// ---------------------------------------------------------------------------
__global__ __launch_bounds__(256) void prel_kernel(const float* __restrict__ p_rel_xj,
                                                   const float* __restrict__ p_rel_xi) {
    int blk = blockIdx.x;
    int b = blk >> 3;
    int branch = (blk >> 2) & 1;
    int d = blk & 3;
    const float* A = g_pt + (((size_t)b * 2 + branch) * DD + d) * 4096;
    const float* R = (branch == 0 ? p_rel_xj : p_rel_xi) + (size_t)d * 4096;

    __shared__ float As[4096];
    __shared__ float Rs[4096];
    __shared__ float red[256];
    __shared__ float cs[64];

    int tid = threadIdx.x;
    for (int i = tid; i < 4096; i += 256) { As[i] = A[i]; Rs[i] = R[i]; }
    __syncthreads();

    int r = tid >> 4, c = tid & 15;
    float g[4][4];
#pragma unroll
    for (int i = 0; i < 4; i++)
#pragma unroll
        for (int j = 0; j < 4; j++) g[i][j] = 0.f;
    for (int k = 0; k < 64; k++) {
        float a[4], bv[4];
#pragma unroll
        for (int i = 0; i < 4; i++) a[i] = As[(r * 4 + i) * 64 + k];
#pragma unroll
        for (int j = 0; j < 4; j++) bv[j] = Rs[k * 64 + c * 4 + j];
#pragma unroll
        for (int i = 0; i < 4; i++)
#pragma unroll
            for (int j = 0; j < 4; j++) g[i][j] += a[i] * bv[j];
    }
    __syncthreads();
#pragma unroll
    for (int i = 0; i < 4; i++)
#pragma unroll
        for (int j = 0; j < 4; j++)
            As[(r * 4 + i) * 64 + c * 4 + j] = g[i][j];
    __syncthreads();

    int p  = tid & 63;
    int rg = tid >> 6;
    float mx = -1e30f;
    for (int row = rg; row < 64; row += 4)
        mx = fmaxf(mx, As[row * 64 + p]);
    red[tid] = mx;
    __syncthreads();
    for (int s = 128; s > 0; s >>= 1) {
        if (tid < s) red[tid] = fmaxf(red[tid], red[tid + s]);
        __syncthreads();
    }
    float gmax = red[0];
    __syncthreads();
    float se = 0.f;
    for (int row = rg; row < 64; row += 4)
        se += expf(As[row * 64 + p] - gmax);
    red[tid] = se;
    __syncthreads();
    if (tid < 64)
        cs[tid] = red[tid] + red[64 + tid] + red[128 + tid] + red[192 + tid];
    __syncthreads();
    if (tid == 0) {
        float t = 0.f;
        for (int i = 0; i < 64; i++) t += cs[i];
        red[0] = t;
    }
    __syncthreads();
    if (tid < 64)
        g_prel[(((size_t)b * 2 + branch) * DD + d) * 64 + tid] = cs[tid] / red[0];
}

// ---------------------------------------------------------------------------
// K6: final combine per batch
// ---------------------------------------------------------------------------
__global__ __launch_bounds__(256) void final_kernel(float* __restrict__ out) {
    int b = blockIdx.x;
    int tid = threadIdx.x;
    __shared__ float fj[64], fi[64];
    __shared__ float red[256], red2[256];

    float accv[16];
#pragma unroll
    for (int i = 0; i < 16; i++) accv[i] = 0.f;

    float xm = g_stats[b * 2 + 0];
    float xs = g_stats[b * 2 + 1];

    for (int d = 0; d < DD; d++) {
        __syncthreads();
        if (tid < 64) {
            size_t ij = (((size_t)b * 2 + 0) * DD + d) * 64 + tid;
            fj[tid] = sqrtf(g_orel[ij] / g_prel[ij]);
        } else if (tid < 128) {
            int p = tid - 64;
            size_t ii = (((size_t)b * 2 + 1) * DD + d) * 64 + p;
            fi[p] = sqrtf(g_orel[ii] / g_prel[ii]);
        }
        __syncthreads();

        const float* ptj = g_pt + (((size_t)b * 2 + 0) * DD + d) * 4096;
        const float* pti = g_pt + (((size_t)b * 2 + 1) * DD + d) * 4096;

        float v[16];
        float s = 0.f, s2 = 0.f;
#pragma unroll
        for (int i = 0; i < 16; i++) {
            int e = i * 256 + tid;
            int p1 = e >> 6, p2 = e & 63;
            float val = ptj[e] * fj[p1] + pti[p2 * 64 + p1] * fi[p2];
            v[i] = val;
            s += val;
            s2 += val * val;
        }
        red[tid] = s; red2[tid] = s2;
        __syncthreads();
        for (int st = 128; st > 0; st >>= 1) {
            if (tid < st) { red[tid] += red[tid + st]; red2[tid] += red2[tid + st]; }
            __syncthreads();
        }
        float sum = red[0], sumsq = red2[0];
        float mu = sum / 4096.0f;
        float var = (sumsq - sum * sum / 4096.0f) / 4095.0f;
        float inv = 1.0f / (sqrtf(var) + EPSV);
#pragma unroll
        for (int i = 0; i < 16; i++)
            accv[i] += (v[i] - mu) * inv * xs + xm;
        __syncthreads();
    }

#pragma unroll
    for (int i = 0; i < 16; i++)
        out[(size_t)b * 4096 + i * 256 + tid] = accv[i];
}

// ---------------------------------------------------------------------------
// Launch
// ---------------------------------------------------------------------------
extern "C" void kernel_launch(void* const* d_in, const int* in_sizes, int n_in,
                              void* d_out, int out_size) {
    const float* x        = (const float*)d_in[0];
    const float* o_xj     = (const float*)d_in[1];
    const float* o_xi     = (const float*)d_in[2];
    const float* p_xj     = (const float*)d_in[3];
    const float* p_xi     = (const float*)d_in[4];
    const float* o_rel_xj = (const float*)d_in[5];
    const float* o_rel_xi = (const float*)d_in[6];
    const float* p_rel_xj = (const float*)d_in[7];
    const float* p_rel_xi = (const float*)d_in[8];
    float* out = (float*)d_out;

    prep_kernel<<<(512 * 512) / 256, 256>>>(o_rel_xj, p_xi, o_rel_xi, p_xj);
    stats_kernel<<<BB, 256>>>(x);
    gemm_s1<false><<<dim3(4, 4, BB), 256>>>(x);   // U = x_b @ Wj
    gemm_s1<true><<<dim3(4, 4, BB), 256>>>(x);    // V = x_b^T @ Wi
    rel1_kernel<<<BB * 8, 256>>>();
    pt_gemm_kernel<<<BB * 8, 256>>>(o_xj, o_xi);
    prel_kernel<<<BB * 8, 256>>>(p_rel_xj, p_rel_xi);
    final_kernel<<<BB, 256>>>(out);
}

// round 17
// speedup vs baseline: 1.5615x; 1.4336x over previous
#include <cuda_runtime.h>
#include <cuda_bf16.h>
#include <math.h>
#include <stdint.h>

// Problem constants
#define BB 128
#define HH 512
#define WW 512
#define PP 64
#define DD 4
#define NHW (HH * WW)
#define EPSV 1e-5f

// ---------------------------------------------------------------------------
// Scratch (device globals)
// ---------------------------------------------------------------------------
static __device__ __nv_bfloat16 g_xhi[(size_t)BB * NHW];   // x  [b][h][w] hi
static __device__ __nv_bfloat16 g_xlo[(size_t)BB * NHW];   // x  lo
static __device__ __nv_bfloat16 g_xThi[(size_t)BB * NHW];  // xT [b][w][h] hi
static __device__ __nv_bfloat16 g_xTlo[(size_t)BB * NHW];  // xT lo
static __device__ __nv_bfloat16 g_WjT_hi[512 * 512];       // Wj^T [n][k] hi
static __device__ __nv_bfloat16 g_WjT_lo[512 * 512];
static __device__ __nv_bfloat16 g_WiT_hi[512 * 512];       // Wi^T [n][k] hi
static __device__ __nv_bfloat16 g_WiT_lo[512 * 512];
static __device__ float g_U[(size_t)BB * 512 * 512];       // x  @ Wj  [b][h][n]
static __device__ float g_V[(size_t)BB * 512 * 512];       // xT @ Wi  [b][w][n]
static __device__ float g_pt[(size_t)BB * 2 * DD * PP * PP];
static __device__ float g_orel[(size_t)BB * 2 * DD * PP];
static __device__ float g_prel[(size_t)BB * 2 * DD * PP];
static __device__ float g_stats[BB * 2];

// ---------------------------------------------------------------------------
// prepw: weight concat + transpose to [n][k] + bf16 hi/lo split
// ---------------------------------------------------------------------------
__global__ void prepw_kernel(const float* __restrict__ o_rel_xj,
                             const float* __restrict__ p_xi,
                             const float* __restrict__ o_rel_xi,
                             const float* __restrict__ p_xj) {
    int idx = blockIdx.x * 256 + threadIdx.x;   // [n][k]
    int n = idx >> 9;
    int k = idx & 511;
    int d = (n >> 6) & 3;
    int p = n & 63;
    int widx = (d * 512 + k) * 64 + p;
    float vj = (n < 256) ? o_rel_xj[widx] : p_xi[widx];
    float vi = (n < 256) ? o_rel_xi[widx] : p_xj[widx];
    __nv_bfloat16 hj = __float2bfloat16(vj);
    __nv_bfloat16 hi = __float2bfloat16(vi);
    g_WjT_hi[idx] = hj;
    g_WjT_lo[idx] = __float2bfloat16(vj - __bfloat162float(hj));
    g_WiT_hi[idx] = hi;
    g_WiT_lo[idx] = __float2bfloat16(vi - __bfloat162float(hi));
}

// ---------------------------------------------------------------------------
// prepx: per-batch transpose + bf16 hi/lo split of x
// ---------------------------------------------------------------------------
__global__ __launch_bounds__(256) void prepx_kernel(const float* __restrict__ x) {
    __shared__ float tile[32][33];
    int b = blockIdx.z;
    const float* xb = x + (size_t)b * NHW;
    int tx = threadIdx.x, ty = threadIdx.y;
    int c = blockIdx.x * 32 + tx;
#pragma unroll
    for (int i = 0; i < 4; i++) {
        int r = blockIdx.y * 32 + ty + i * 8;
        float v = xb[(size_t)r * 512 + c];
        tile[ty + i * 8][tx] = v;
        __nv_bfloat16 h = __float2bfloat16(v);
        size_t o = (size_t)b * NHW + (size_t)r * 512 + c;
        g_xhi[o] = h;
        g_xlo[o] = __float2bfloat16(v - __bfloat162float(h));
    }
    __syncthreads();
    int c2 = blockIdx.y * 32 + tx;  // h index
#pragma unroll
    for (int i = 0; i < 4; i++) {
        int r2 = blockIdx.x * 32 + ty + i * 8;  // w index
        float v = tile[tx][ty + i * 8];         // = x[c2][r2]
        __nv_bfloat16 h = __float2bfloat16(v);
        size_t o = (size_t)b * NHW + (size_t)r2 * 512 + c2;
        g_xThi[o] = h;
        g_xTlo[o] = __float2bfloat16(v - __bfloat162float(h));
    }
}

// ---------------------------------------------------------------------------
// stats: per-batch mean*64 and unbiased std*64 of x
// ---------------------------------------------------------------------------
__global__ __launch_bounds__(256) void stats_kernel(const float* __restrict__ x) {
    int b = blockIdx.x;
    const float4* xb4 = (const float4*)(x + (size_t)b * NHW);
    int tid = threadIdx.x;
    float s = 0.f, s2 = 0.f;
    for (int i = tid; i < NHW / 4; i += 256) {
        float4 v = xb4[i];
        s  += v.x + v.y + v.z + v.w;
        s2 += v.x * v.x + v.y * v.y + v.z * v.z + v.w * v.w;
    }
    __shared__ float rs[256], rs2[256];
    rs[tid] = s; rs2[tid] = s2;
    __syncthreads();
    for (int st = 128; st > 0; st >>= 1) {
        if (tid < st) { rs[tid] += rs[tid + st]; rs2[tid] += rs2[tid + st]; }
        __syncthreads();
    }
    if (tid == 0) {
        float n = (float)NHW;
        float sum = rs[0], sumsq = rs2[0];
        float mean = sum / n;
        float var = (sumsq - sum * sum / n) / (n - 1.0f);
        g_stats[b * 2 + 0] = mean * 64.0f;
        g_stats[b * 2 + 1] = sqrtf(var) * 64.0f;
    }
}

// ---------------------------------------------------------------------------
// gemm_mma: tensor-core GEMM via mma.sync bf16 (hi/lo 3-term compensation).
// C[512,512] = A[512,512] @ B^T (B stored [n][k]).  CTA tile 128x128, 8 warps,
// warp tile 32m x 64n, k-chunk 32 (2 x k16 steps).
// WHICH=0: A = x (g_xhi/lo),  B = WjT, C = g_U.
// WHICH=1: A = xT (g_xThi/lo), B = WiT, C = g_V.
// ---------------------------------------------------------------------------
#define SMSTRIDE 40   // halfs per smem row (32 data + 8 pad); 80 B

__device__ __forceinline__ void mma_bf16(float* c, const uint32_t* a,
                                         uint32_t b0, uint32_t b1) {
    asm volatile(
        "mma.sync.aligned.m16n8k16.row.col.f32.bf16.bf16.f32 "
        "{%0,%1,%2,%3}, {%4,%5,%6,%7}, {%8,%9}, {%0,%1,%2,%3};"
        : "+f"(c[0]), "+f"(c[1]), "+f"(c[2]), "+f"(c[3])
        : "r"(a[0]), "r"(a[1]), "r"(a[2]), "r"(a[3]), "r"(b0), "r"(b1));
}

template <int WHICH>
__global__ __launch_bounds__(256) void gemm_mma() {
    const int b  = blockIdx.z;
    const int bm = blockIdx.y * 128;
    const int bn = blockIdx.x * 128;

    const __nv_bfloat16* Ahg = (WHICH == 0 ? g_xhi : g_xThi) + (size_t)b * NHW;
    const __nv_bfloat16* Alg = (WHICH == 0 ? g_xlo : g_xTlo) + (size_t)b * NHW;
    const __nv_bfloat16* Bhg = (WHICH == 0 ? g_WjT_hi : g_WiT_hi);
    const __nv_bfloat16* Blg = (WHICH == 0 ? g_WjT_lo : g_WiT_lo);
    float* C = (WHICH == 0 ? g_U : g_V) + (size_t)b * NHW;

    __shared__ unsigned short Ah[128][SMSTRIDE];
    __shared__ unsigned short Al[128][SMSTRIDE];
    __shared__ unsigned short Bh[128][SMSTRIDE];
    __shared__ unsigned short Bl[128][SMSTRIDE];

    const int tid  = threadIdx.x;
    const int lane = tid & 31;
    const int wid  = tid >> 5;
    const int wm = (wid >> 1) * 32;   // 0,32,64,96
    const int wn = (wid & 1) * 64;    // 0,64
    const int grp = lane >> 2;        // 0..7
    const int tig = lane & 3;         // 0..3

    float acc[2][8][4];
#pragma unroll
    for (int mt = 0; mt < 2; mt++)
#pragma unroll
        for (int nt = 0; nt < 8; nt++)
#pragma unroll
            for (int q = 0; q < 4; q++) acc[mt][nt][q] = 0.f;

    const int lrow = tid >> 2;          // 0..63
    const int lkof = (tid & 3) * 8;     // 0,8,16,24

    for (int k0 = 0; k0 < 512; k0 += 32) {
        // ---- load tiles: 128 rows x 32 k halfs per array, 2 passes ----
#pragma unroll
        for (int p = 0; p < 2; p++) {
            int am = p * 64 + lrow;
            size_t ga = (size_t)(bm + am) * 512 + k0 + lkof;
            *(uint4*)&Ah[am][lkof] = *(const uint4*)(Ahg + ga);
            *(uint4*)&Al[am][lkof] = *(const uint4*)(Alg + ga);
            size_t gb = (size_t)(bn + am) * 512 + k0 + lkof;
            *(uint4*)&Bh[am][lkof] = *(const uint4*)(Bhg + gb);
            *(uint4*)&Bl[am][lkof] = *(const uint4*)(Blg + gb);
        }
        __syncthreads();

#pragma unroll
        for (int kb = 0; kb < 32; kb += 16) {
            // A fragments (2 m16 tiles), hi + lo
            uint32_t ah[2][4], al[2][4];
#pragma unroll
            for (int mt = 0; mt < 2; mt++) {
                int r0 = wm + mt * 16 + grp;
                int cc = kb + 2 * tig;
                ah[mt][0] = *(const uint32_t*)&Ah[r0][cc];
                ah[mt][1] = *(const uint32_t*)&Ah[r0 + 8][cc];
                ah[mt][2] = *(const uint32_t*)&Ah[r0][cc + 8];
                ah[mt][3] = *(const uint32_t*)&Ah[r0 + 8][cc + 8];
                al[mt][0] = *(const uint32_t*)&Al[r0][cc];
                al[mt][1] = *(const uint32_t*)&Al[r0 + 8][cc];
                al[mt][2] = *(const uint32_t*)&Al[r0][cc + 8];
                al[mt][3] = *(const uint32_t*)&Al[r0 + 8][cc + 8];
            }
#pragma unroll
            for (int nt = 0; nt < 8; nt++) {
                int nr = wn + nt * 8 + grp;
                int cc = kb + 2 * tig;
                uint32_t bh0 = *(const uint32_t*)&Bh[nr][cc];
                uint32_t bh1 = *(const uint32_t*)&Bh[nr][cc + 8];
                uint32_t bl0 = *(const uint32_t*)&Bl[nr][cc];
                uint32_t bl1 = *(const uint32_t*)&Bl[nr][cc + 8];
#pragma unroll
                for (int mt = 0; mt < 2; mt++) {
                    mma_bf16(acc[mt][nt], ah[mt], bh0, bh1);  // hi*hi
                    mma_bf16(acc[mt][nt], al[mt], bh0, bh1);  // lo*hi
                    mma_bf16(acc[mt][nt], ah[mt], bl0, bl1);  // hi*lo
                }
            }
        }
        __syncthreads();
    }

    // ---- epilogue: write C fragments ----
#pragma unroll
    for (int mt = 0; mt < 2; mt++) {
#pragma unroll
        for (int nt = 0; nt < 8; nt++) {
            int row = bm + wm + mt * 16 + grp;
            int col = bn + wn + nt * 8 + 2 * tig;
            float2 v0 = make_float2(acc[mt][nt][0], acc[mt][nt][1]);
            float2 v1 = make_float2(acc[mt][nt][2], acc[mt][nt][3]);
            *(float2*)&C[(size_t)row * 512 + col]       = v0;
            *(float2*)&C[(size_t)(row + 8) * 512 + col] = v1;
        }
    }
}

// ---------------------------------------------------------------------------
// rel1: o_rel flat-softmax column sums over [512,64] slabs of U / V.
// ---------------------------------------------------------------------------
__global__ __launch_bounds__(256) void rel1_kernel() {
    int blk = blockIdx.x;
    int b = blk >> 3;
    int branch = (blk >> 2) & 1;
    int d = blk & 3;
    const float* base = (branch ? g_V : g_U) + (size_t)b * NHW + d * 64;

    int tid = threadIdx.x;
    int p  = tid & 63;
    int rg = tid >> 6;

    __shared__ float red[256];
    __shared__ float cs[64];

    float mx = -1e30f;
    for (int h = rg; h < 512; h += 4)
        mx = fmaxf(mx, base[(size_t)h * 512 + p]);
    red[tid] = mx;
    __syncthreads();
    for (int s = 128; s > 0; s >>= 1) {
        if (tid < s) red[tid] = fmaxf(red[tid], red[tid + s]);
        __syncthreads();
    }
    float gmax = red[0];
    __syncthreads();

    float se = 0.f;
    for (int h = rg; h < 512; h += 4)
        se += expf(base[(size_t)h * 512 + p] - gmax);
    red[tid] = se;
    __syncthreads();
    if (tid < 64)
        cs[tid] = red[tid] + red[64 + tid] + red[128 + tid] + red[192 + tid];
    __syncthreads();
    if (tid == 0) {
        float t = 0.f;
        for (int i = 0; i < 64; i++) t += cs[i];
        red[0] = t;
    }
    __syncthreads();
    if (tid < 64)
        g_orel[(((size_t)b * 2 + branch) * DD + d) * 64 + tid] = cs[tid] / red[0];
}

// ---------------------------------------------------------------------------
// pt_gemm: p_t[b][branch][d] (64x64)
// ---------------------------------------------------------------------------
__global__ __launch_bounds__(256) void pt_gemm_kernel(const float* __restrict__ o_xj,
                                                      const float* __restrict__ o_xi) {
    int blk = blockIdx.x;
    int b = blk >> 3;
    int branch = (blk >> 2) & 1;
    int d = blk & 3;
    const float* Aw = (branch == 0 ? o_xj : o_xi) + (size_t)d * 512 * 64;
    const float* Bm = (branch == 0 ? g_V : g_U) + (size_t)b * NHW + 256 + d * 64;

    __shared__ float As[32][68];
    __shared__ float Bs[32][68];

    int tid = threadIdx.x;
    int r = tid >> 4, c = tid & 15;
    float acc[4][4];
#pragma unroll
    for (int i = 0; i < 4; i++)
#pragma unroll
        for (int j = 0; j < 4; j++) acc[i][j] = 0.f;

    for (int k0 = 0; k0 < 512; k0 += 32) {
        int k  = tid >> 3;
        int pq = (tid & 7) * 8;
        float4 a0 = *(const float4*)&Aw[(size_t)(k0 + k) * 64 + pq];
        float4 a1 = *(const float4*)&Aw[(size_t)(k0 + k) * 64 + pq + 4];
        *(float4*)&As[k][pq]     = a0;
        *(float4*)&As[k][pq + 4] = a1;
        float4 b0 = *(const float4*)&Bm[(size_t)(k0 + k) * 512 + pq];
        float4 b1 = *(const float4*)&Bm[(size_t)(k0 + k) * 512 + pq + 4];
        *(float4*)&Bs[k][pq]     = b0;
        *(float4*)&Bs[k][pq + 4] = b1;
        __syncthreads();
#pragma unroll
        for (int k2 = 0; k2 < 32; k2++) {
            float a[4], bv[4];
#pragma unroll
            for (int i = 0; i < 4; i++) a[i] = As[k2][r * 4 + i];
#pragma unroll
            for (int j = 0; j < 4; j++) bv[j] = Bs[k2][c * 4 + j];
#pragma unroll
            for (int i = 0; i < 4; i++)
#pragma unroll
                for (int j = 0; j < 4; j++) acc[i][j] += a[i] * bv[j];
        }
        __syncthreads();
    }

    float* out = g_pt + (((size_t)b * 2 + branch) * DD + d) * 4096;
#pragma unroll
    for (int i = 0; i < 4; i++) {
        float4 v = make_float4(acc[i][0], acc[i][1], acc[i][2], acc[i][3]);
        *(float4*)&out[(size_t)(r * 4 + i) * 64 + c * 4] = v;
    }
}

// ---------------------------------------------------------------------------
// prel: G = p_t @ p_rel (64x64), then flat-softmax column sums.
// ---------------------------------------------------------------------------
__global__ __launch_bounds__(256) void prel_kernel(const float* __restrict__ p_rel_xj,
                                                   const float* __restrict__ p_rel_xi) {
    int blk = blockIdx.x;
    int b = blk >> 3;
    int branch = (blk >> 2) & 1;
    int d = blk & 3;
    const float* A = g_pt + (((size_t)b * 2 + branch) * DD + d) * 4096;
    const float* R = (branch == 0 ? p_rel_xj : p_rel_xi) + (size_t)d * 4096;

    __shared__ float As[4096];
    __shared__ float Rs[4096];
    __shared__ float red[256];
    __shared__ float cs[64];

    int tid = threadIdx.x;
    for (int i = tid; i < 4096; i += 256) { As[i] = A[i]; Rs[i] = R[i]; }
    __syncthreads();

    int r = tid >> 4, c = tid & 15;
    float g[4][4];
#pragma unroll
    for (int i = 0; i < 4; i++)
#pragma unroll
        for (int j = 0; j < 4; j++) g[i][j] = 0.f;
    for (int k = 0; k < 64; k++) {
        float a[4], bv[4];
#pragma unroll
        for (int i = 0; i < 4; i++) a[i] = As[(r * 4 + i) * 64 + k];
#pragma unroll
        for (int j = 0; j < 4; j++) bv[j] = Rs[k * 64 + c * 4 + j];
#pragma unroll
        for (int i = 0; i < 4; i++)
#pragma unroll
            for (int j = 0; j < 4; j++) g[i][j] += a[i] * bv[j];
    }
    __syncthreads();
#pragma unroll
    for (int i = 0; i < 4; i++)
#pragma unroll
        for (int j = 0; j < 4; j++)
            As[(r * 4 + i) * 64 + c * 4 + j] = g[i][j];
    __syncthreads();

    int p  = tid & 63;
    int rg = tid >> 6;
    float mx = -1e30f;
    for (int row = rg; row < 64; row += 4)
        mx = fmaxf(mx, As[row * 64 + p]);
    red[tid] = mx;
    __syncthreads();
    for (int s = 128; s > 0; s >>= 1) {
        if (tid < s) red[tid] = fmaxf(red[tid], red[tid + s]);
        __syncthreads();
    }
    float gmax = red[0];
    __syncthreads();
    float se = 0.f;
    for (int row = rg; row < 64; row += 4)
        se += expf(As[row * 64 + p] - gmax);
    red[tid] = se;
    __syncthreads();
    if (tid < 64)
        cs[tid] = red[tid] + red[64 + tid] + red[128 + tid] + red[192 + tid];
    __syncthreads();
    if (tid == 0) {
        float t = 0.f;
        for (int i = 0; i < 64; i++) t += cs[i];
        red[0] = t;
    }
    __syncthreads();
    if (tid < 64)
        g_prel[(((size_t)b * 2 + branch) * DD + d) * 64 + tid] = cs[tid] / red[0];
}

// ---------------------------------------------------------------------------
// final combine per batch
// ---------------------------------------------------------------------------
__global__ __launch_bounds__(256) void final_kernel(float* __restrict__ out) {
    int b = blockIdx.x;
    int tid = threadIdx.x;
    __shared__ float fj[64], fi[64];
    __shared__ float red[256], red2[256];

    float accv[16];
#pragma unroll
    for (int i = 0; i < 16; i++) accv[i] = 0.f;

    float xm = g_stats[b * 2 + 0];
    float xs = g_stats[b * 2 + 1];

    for (int d = 0; d < DD; d++) {
        __syncthreads();
        if (tid < 64) {
            size_t ij = (((size_t)b * 2 + 0) * DD + d) * 64 + tid;
            fj[tid] = sqrtf(g_orel[ij] / g_prel[ij]);
        } else if (tid < 128) {
            int p = tid - 64;
            size_t ii = (((size_t)b * 2 + 1) * DD + d) * 64 + p;
            fi[p] = sqrtf(g_orel[ii] / g_prel[ii]);
        }
        __syncthreads();

        const float* ptj = g_pt + (((size_t)b * 2 + 0) * DD + d) * 4096;
        const float* pti = g_pt + (((size_t)b * 2 + 1) * DD + d) * 4096;

        float v[16];
        float s = 0.f, s2 = 0.f;
#pragma unroll
        for (int i = 0; i < 16; i++) {
            int e = i * 256 + tid;
            int p1 = e >> 6, p2 = e & 63;
            float val = ptj[e] * fj[p1] + pti[p2 * 64 + p1] * fi[p2];
            v[i] = val;
            s += val;
            s2 += val * val;
        }
        red[tid] = s; red2[tid] = s2;
        __syncthreads();
        for (int st = 128; st > 0; st >>= 1) {
            if (tid < st) { red[tid] += red[tid + st]; red2[tid] += red2[tid + st]; }
            __syncthreads();
        }
        float sum = red[0], sumsq = red2[0];
        float mu = sum / 4096.0f;
        float var = (sumsq - sum * sum / 4096.0f) / 4095.0f;
        float inv = 1.0f / (sqrtf(var) + EPSV);
#pragma unroll
        for (int i = 0; i < 16; i++)
            accv[i] += (v[i] - mu) * inv * xs + xm;
        __syncthreads();
    }

#pragma unroll
    for (int i = 0; i < 16; i++)
        out[(size_t)b * 4096 + i * 256 + tid] = accv[i];
}

// ---------------------------------------------------------------------------
// Launch
// ---------------------------------------------------------------------------
extern "C" void kernel_launch(void* const* d_in, const int* in_sizes, int n_in,
                              void* d_out, int out_size) {
    const float* x        = (const float*)d_in[0];
    const float* o_xj     = (const float*)d_in[1];
    const float* o_xi     = (const float*)d_in[2];
    const float* p_xj     = (const float*)d_in[3];
    const float* p_xi     = (const float*)d_in[4];
    const float* o_rel_xj = (const float*)d_in[5];
    const float* o_rel_xi = (const float*)d_in[6];
    const float* p_rel_xj = (const float*)d_in[7];
    const float* p_rel_xi = (const float*)d_in[8];
    float* out = (float*)d_out;

    prepw_kernel<<<(512 * 512) / 256, 256>>>(o_rel_xj, p_xi, o_rel_xi, p_xj);
    prepx_kernel<<<dim3(16, 16, BB), dim3(32, 8)>>>(x);
    stats_kernel<<<BB, 256>>>(x);
    gemm_mma<0><<<dim3(4, 4, BB), 256>>>();   // U = x @ Wj
    gemm_mma<1><<<dim3(4, 4, BB), 256>>>();   // V = xT @ Wi
    rel1_kernel<<<BB * 8, 256>>>();
    pt_gemm_kernel<<<BB * 8, 256>>>(o_xj, o_xi);
    prel_kernel<<<BB * 8, 256>>>(p_rel_xj, p_rel_xi);
    final_kernel<<<BB, 256>>>(out);
}